// round 12
// baseline (speedup 1.0000x reference)
#include <cuda_runtime.h>
#include <cuda_fp16.h>

// Problem constants (fixed shapes from setup_inputs)
#define BB 2
#define CC 3
#define HH 512
#define WW 512
#define FF 5
#define TT 25
#define HWSZ (HH * WW)

// Channel-interleaved fp16 copy of the input: [B, H, W, 4 halves] (4th unused).
// 2 * 262144 * 8B = 4 MB static device scratch.
__device__ uint2 g_packed[BB * HWSZ];

// Pack 4 pixels per thread: 3x float4 loads, 2x uint4 stores.
__global__ __launch_bounds__(256) void pack_kernel(const float* __restrict__ inp) {
    int tid = blockIdx.x * blockDim.x + threadIdx.x;   // B*H*W/4 threads
    int b = tid >> 16;                                  // (HWSZ/4) = 2^16
    int q = tid & (HWSZ / 4 - 1);
    int p = q * 4;
    const float* __restrict__ inb = inp + b * (CC * HWSZ) + p;
    float4 c0 = __ldg((const float4*)(inb));
    float4 c1 = __ldg((const float4*)(inb + HWSZ));
    float4 c2 = __ldg((const float4*)(inb + 2 * HWSZ));

    __half2 a01 = __floats2half2_rn(c0.x, c1.x);
    __half2 a2z = __floats2half2_rn(c2.x, 0.0f);
    __half2 b01 = __floats2half2_rn(c0.y, c1.y);
    __half2 b2z = __floats2half2_rn(c2.y, 0.0f);
    __half2 d01 = __floats2half2_rn(c0.z, c1.z);
    __half2 d2z = __floats2half2_rn(c2.z, 0.0f);
    __half2 e01 = __floats2half2_rn(c0.w, c1.w);
    __half2 e2z = __floats2half2_rn(c2.w, 0.0f);

    uint4 lo, hi;
    lo.x = *(unsigned int*)&a01; lo.y = *(unsigned int*)&a2z;
    lo.z = *(unsigned int*)&b01; lo.w = *(unsigned int*)&b2z;
    hi.x = *(unsigned int*)&d01; hi.y = *(unsigned int*)&d2z;
    hi.z = *(unsigned int*)&e01; hi.w = *(unsigned int*)&e2z;

    uint4* dst = (uint4*)(g_packed + b * HWSZ + p);
    dst[0] = lo;
    dst[1] = hi;
}

// Main kernel: 2 horizontally-adjacent pixels per thread (R9 winner),
// restructured as nested fy/fx loops with lazy filter loads to cut register
// pressure; __launch_bounds__(256, 5) targets 5 blocks/SM (40 warps).
__global__ __launch_bounds__(256, 5) void dsepconv_kernel(
    const float* __restrict__ vert,    // [B,F,H,W]
    const float* __restrict__ horiz,   // [B,F,H,W]
    const float* __restrict__ offx,    // [B,T,H,W]  (used for y coordinate)
    const float* __restrict__ offy,    // [B,T,H,W]  (used for x coordinate)
    const float* __restrict__ mask,    // [B,T,H,W]
    float* __restrict__ out)           // [B,C,H,W]
{
    int tid = blockIdx.x * blockDim.x + threadIdx.x;   // B*H*W/2 threads
    int b = tid >> 17;                                  // HWSZ/2 = 2^17
    int pp = tid & (HWSZ / 2 - 1);
    int p = pp * 2;                                     // even pixel index
    int h = p >> 9;
    int w = p & (WW - 1);                               // even

    const uint2* __restrict__ gp = g_packed + b * HWSZ;
    const float* __restrict__ vbase = vert  + b * (FF * HWSZ) + p;
    const float* __restrict__ hbase = horiz + b * (FF * HWSZ) + p;

    const float2* __restrict__ oxp = (const float2*)(offx + b * (TT * HWSZ) + p);
    const float2* __restrict__ oyp = (const float2*)(offy + b * (TT * HWSZ) + p);
    const float2* __restrict__ mkp = (const float2*)(mask + b * (TT * HWSZ) + p);

    float a0A = 0.f, a1A = 0.f, a2A = 0.f;   // pixel A accumulators
    float a0B = 0.f, a1B = 0.f, a2B = 0.f;   // pixel B accumulators

#pragma unroll
    for (int fy = 0; fy < FF; fy++) {
        // vertical filter value for this tap row (shared by 5 inner taps)
        float2 vv = __ldg((const float2*)(vbase + fy * HWSZ));

#pragma unroll
        for (int fx = 0; fx < FF; fx++) {
            const int t = fy * FF + fx;

            float2 o_x = __ldg(oxp + t * (HWSZ / 2));   // -> y coordinate (faithful swap)
            float2 o_y = __ldg(oyp + t * (HWSZ / 2));   // -> x coordinate
            float2 m   = __ldg(mkp + t * (HWSZ / 2));
            // horizontal filter value (L1 hit after first fy iteration)
            float2 hh  = __ldg((const float2*)(hbase + fx * HWSZ));

            // ix = clamp(offy + w + fx - 1.5, -0.5, W-0.5)  (exact reduction of reference)
            float uA = o_y.x + (float)(w + fx) - 1.0f;
            float uB = o_y.y + (float)(w + 1 + fx) - 1.0f;
            float vA = o_x.x + (float)(h + fy) - 1.0f;
            float vB = o_x.y + (float)(h + fy) - 1.0f;

            float ixA = fminf(fmaxf(uA - 0.5f, -0.5f), (float)WW - 0.5f);
            float ixB = fminf(fmaxf(uB - 0.5f, -0.5f), (float)WW - 0.5f);
            float iyA = fminf(fmaxf(vA - 0.5f, -0.5f), (float)HH - 0.5f);
            float iyB = fminf(fmaxf(vB - 0.5f, -0.5f), (float)HH - 0.5f);

            float fxA = floorf(ixA), fxB = floorf(ixB);
            float fyA = floorf(iyA), fyB = floorf(iyB);
            float wx1A = ixA - fxA, wx1B = ixB - fxB;
            float wy1A = iyA - fyA, wy1B = iyB - fyB;

            // x0 in [-1,511], so one-sided clamps suffice
            int x0A = (int)fxA, x0B = (int)fxB;
            int y0A = (int)fyA, y0B = (int)fyB;
            int x0iA = max(x0A, 0);
            int x1iA = min(x0A + 1, WW - 1);
            int y0iA = max(y0A, 0);
            int y1iA = min(y0A + 1, HH - 1);
            int x0iB = max(x0B, 0);
            int x1iB = min(x0B + 1, WW - 1);
            int y0iB = max(y0B, 0);
            int y1iB = min(y0B + 1, HH - 1);

            int r0A = y0iA * WW, r1A = y1iA * WW;
            int r0B = y0iB * WW, r1B = y1iB * WW;

            // Issue all 8 gathers up front for MLP
            uint2 q00A = __ldg(gp + r0A + x0iA);
            uint2 q01A = __ldg(gp + r0A + x1iA);
            uint2 q10A = __ldg(gp + r1A + x0iA);
            uint2 q11A = __ldg(gp + r1A + x1iA);
            uint2 q00B = __ldg(gp + r0B + x0iB);
            uint2 q01B = __ldg(gp + r0B + x1iB);
            uint2 q10B = __ldg(gp + r1B + x0iB);
            uint2 q11B = __ldg(gp + r1B + x1iB);

            float coefA = vv.x * hh.x * m.x;
            float coefB = vv.y * hh.y * m.y;

            float w00A = coefA * (1.0f - wy1A) * (1.0f - wx1A);
            float w01A = coefA * (1.0f - wy1A) * wx1A;
            float w10A = coefA * wy1A * (1.0f - wx1A);
            float w11A = coefA * wy1A * wx1A;
            float w00B = coefB * (1.0f - wy1B) * (1.0f - wx1B);
            float w01B = coefB * (1.0f - wy1B) * wx1B;
            float w10B = coefB * wy1B * (1.0f - wx1B);
            float w11B = coefB * wy1B * wx1B;

            // Pixel A
            {
                float2 f01 = __half22float2(*reinterpret_cast<__half2*>(&q00A.x));
                float  f2  = __low2float(*reinterpret_cast<__half2*>(&q00A.y));
                a0A = fmaf(w00A, f01.x, a0A); a1A = fmaf(w00A, f01.y, a1A); a2A = fmaf(w00A, f2, a2A);
            }
            {
                float2 f01 = __half22float2(*reinterpret_cast<__half2*>(&q01A.x));
                float  f2  = __low2float(*reinterpret_cast<__half2*>(&q01A.y));
                a0A = fmaf(w01A, f01.x, a0A); a1A = fmaf(w01A, f01.y, a1A); a2A = fmaf(w01A, f2, a2A);
            }
            {
                float2 f01 = __half22float2(*reinterpret_cast<__half2*>(&q10A.x));
                float  f2  = __low2float(*reinterpret_cast<__half2*>(&q10A.y));
                a0A = fmaf(w10A, f01.x, a0A); a1A = fmaf(w10A, f01.y, a1A); a2A = fmaf(w10A, f2, a2A);
            }
            {
                float2 f01 = __half22float2(*reinterpret_cast<__half2*>(&q11A.x));
                float  f2  = __low2float(*reinterpret_cast<__half2*>(&q11A.y));
                a0A = fmaf(w11A, f01.x, a0A); a1A = fmaf(w11A, f01.y, a1A); a2A = fmaf(w11A, f2, a2A);
            }
            // Pixel B
            {
                float2 f01 = __half22float2(*reinterpret_cast<__half2*>(&q00B.x));
                float  f2  = __low2float(*reinterpret_cast<__half2*>(&q00B.y));
                a0B = fmaf(w00B, f01.x, a0B); a1B = fmaf(w00B, f01.y, a1B); a2B = fmaf(w00B, f2, a2B);
            }
            {
                float2 f01 = __half22float2(*reinterpret_cast<__half2*>(&q01B.x));
                float  f2  = __low2float(*reinterpret_cast<__half2*>(&q01B.y));
                a0B = fmaf(w01B, f01.x, a0B); a1B = fmaf(w01B, f01.y, a1B); a2B = fmaf(w01B, f2, a2B);
            }
            {
                float2 f01 = __half22float2(*reinterpret_cast<__half2*>(&q10B.x));
                float  f2  = __low2float(*reinterpret_cast<__half2*>(&q10B.y));
                a0B = fmaf(w10B, f01.x, a0B); a1B = fmaf(w10B, f01.y, a1B); a2B = fmaf(w10B, f2, a2B);
            }
            {
                float2 f01 = __half22float2(*reinterpret_cast<__half2*>(&q11B.x));
                float  f2  = __low2float(*reinterpret_cast<__half2*>(&q11B.y));
                a0B = fmaf(w11B, f01.x, a0B); a1B = fmaf(w11B, f01.y, a1B); a2B = fmaf(w11B, f2, a2B);
            }
        }
    }

    float* ob = out + b * (CC * HWSZ) + p;
    *(float2*)(ob)            = make_float2(a0A, a0B);
    *(float2*)(ob + HWSZ)     = make_float2(a1A, a1B);
    *(float2*)(ob + 2 * HWSZ) = make_float2(a2A, a2B);
}

extern "C" void kernel_launch(void* const* d_in, const int* in_sizes, int n_in,
                              void* d_out, int out_size) {
    const float* inp   = (const float*)d_in[0];
    const float* vert  = (const float*)d_in[1];
    const float* horiz = (const float*)d_in[2];
    const float* offx  = (const float*)d_in[3];
    const float* offy  = (const float*)d_in[4];
    const float* mask  = (const float*)d_in[5];
    float* out = (float*)d_out;

    pack_kernel<<<BB * HWSZ / 4 / 256, 256>>>(inp);                                     // 512 blocks
    dsepconv_kernel<<<BB * HWSZ / 2 / 256, 256>>>(vert, horiz, offx, offy, mask, out);  // 1024 blocks
}

// round 14
// speedup vs baseline: 1.0461x; 1.0461x over previous
#include <cuda_runtime.h>
#include <cuda_fp16.h>
#include <cstdint>

// Problem constants (fixed shapes from setup_inputs)
#define BB 2
#define CC 3
#define HH 512
#define WW 512
#define FF 5
#define TT 25
#define HWSZ (HH * WW)

#define DEPTH 6   // cp.async prefetch depth (taps in flight)

// Channel-interleaved fp16 copy of the input: [B, H, W, 4 halves] (4th unused).
__device__ uint2 g_packed[BB * HWSZ];

// Pack 4 pixels per thread: 3x float4 loads, 2x uint4 stores.
__global__ __launch_bounds__(256) void pack_kernel(const float* __restrict__ inp) {
    int tid = blockIdx.x * blockDim.x + threadIdx.x;   // B*H*W/4 threads
    int b = tid >> 16;
    int q = tid & (HWSZ / 4 - 1);
    int p = q * 4;
    const float* __restrict__ inb = inp + b * (CC * HWSZ) + p;
    float4 c0 = __ldg((const float4*)(inb));
    float4 c1 = __ldg((const float4*)(inb + HWSZ));
    float4 c2 = __ldg((const float4*)(inb + 2 * HWSZ));

    __half2 a01 = __floats2half2_rn(c0.x, c1.x);
    __half2 a2z = __floats2half2_rn(c2.x, 0.0f);
    __half2 b01 = __floats2half2_rn(c0.y, c1.y);
    __half2 b2z = __floats2half2_rn(c2.y, 0.0f);
    __half2 d01 = __floats2half2_rn(c0.z, c1.z);
    __half2 d2z = __floats2half2_rn(c2.z, 0.0f);
    __half2 e01 = __floats2half2_rn(c0.w, c1.w);
    __half2 e2z = __floats2half2_rn(c2.w, 0.0f);

    uint4 lo, hi;
    lo.x = *(unsigned int*)&a01; lo.y = *(unsigned int*)&a2z;
    lo.z = *(unsigned int*)&b01; lo.w = *(unsigned int*)&b2z;
    hi.x = *(unsigned int*)&d01; hi.y = *(unsigned int*)&d2z;
    hi.z = *(unsigned int*)&e01; hi.w = *(unsigned int*)&e2z;

    uint4* dst = (uint4*)(g_packed + b * HWSZ + p);
    dst[0] = lo;
    dst[1] = hi;
}

__device__ __forceinline__ void cp_async8(unsigned int smem_addr, const void* gptr) {
    asm volatile("cp.async.ca.shared.global [%0], [%1], 8;\n"
                 :: "r"(smem_addr), "l"(gptr));
}
__device__ __forceinline__ void cp_commit() {
    asm volatile("cp.async.commit_group;\n" ::: "memory");
}
template <int N>
__device__ __forceinline__ void cp_wait() {
    asm volatile("cp.async.wait_group %0;\n" :: "n"(N) : "memory");
}

// Main kernel: R9 structure (2 horizontally-adjacent pixels per thread,
// 8 gathers batched) + cp.async smem ring prefetch for the streaming
// offx/offy/mask loads. No __syncthreads: each thread consumes only its own
// prefetched bytes, so per-thread cp.async group ordering is sufficient.
__global__ __launch_bounds__(256) void dsepconv_kernel(
    const float* __restrict__ vert,    // [B,F,H,W]
    const float* __restrict__ horiz,   // [B,F,H,W]
    const float* __restrict__ offx,    // [B,T,H,W]  (used for y coordinate)
    const float* __restrict__ offy,    // [B,T,H,W]  (used for x coordinate)
    const float* __restrict__ mask,    // [B,T,H,W]
    float* __restrict__ out)           // [B,C,H,W]
{
    __shared__ float2 ring[DEPTH][3][256];   // 36 KB

    int tx  = threadIdx.x;
    int tid = blockIdx.x * blockDim.x + tx;   // B*H*W/2 threads
    int b = tid >> 17;
    int pp = tid & (HWSZ / 2 - 1);
    int p = pp * 2;                            // even pixel index
    int h = p >> 9;
    int w = p & (WW - 1);

    const uint2* __restrict__ gp = g_packed + b * HWSZ;

    const float2* __restrict__ oxp = (const float2*)(offx + b * (TT * HWSZ) + p);
    const float2* __restrict__ oyp = (const float2*)(offy + b * (TT * HWSZ) + p);
    const float2* __restrict__ mkp = (const float2*)(mask + b * (TT * HWSZ) + p);

    // Kick off the prefetch pipeline for taps 0..DEPTH-1
#pragma unroll
    for (int t = 0; t < DEPTH; t++) {
        unsigned int s0 = (unsigned int)__cvta_generic_to_shared(&ring[t][0][tx]);
        unsigned int s1 = (unsigned int)__cvta_generic_to_shared(&ring[t][1][tx]);
        unsigned int s2 = (unsigned int)__cvta_generic_to_shared(&ring[t][2][tx]);
        cp_async8(s0, oxp + t * (HWSZ / 2));
        cp_async8(s1, oyp + t * (HWSZ / 2));
        cp_async8(s2, mkp + t * (HWSZ / 2));
        cp_commit();
    }

    // Preload separable filter values (overlaps with pipeline fill)
    float2 vv[FF], hhv[FF];
#pragma unroll
    for (int f = 0; f < FF; f++) {
        vv[f]  = __ldg((const float2*)(vert  + (b * FF + f) * HWSZ + p));
        hhv[f] = __ldg((const float2*)(horiz + (b * FF + f) * HWSZ + p));
    }

    float a0A = 0.f, a1A = 0.f, a2A = 0.f;
    float a0B = 0.f, a1B = 0.f, a2B = 0.f;

#pragma unroll
    for (int t = 0; t < TT; t++) {
        const int fy = t / FF;
        const int fx = t % FF;
        const int slot = t % DEPTH;

        // Wait for tap t's group (DEPTH-1 younger groups may remain in flight)
        cp_wait<DEPTH - 1>();

        float2 o_x = ring[slot][0][tx];   // -> y coordinate (faithful swap)
        float2 o_y = ring[slot][1][tx];   // -> x coordinate
        float2 m   = ring[slot][2][tx];

        // Refill this slot with tap t+DEPTH (or commit an empty group to keep
        // the wait_group bookkeeping uniform)
        if (t + DEPTH < TT) {
            const int tn = t + DEPTH;
            unsigned int s0 = (unsigned int)__cvta_generic_to_shared(&ring[slot][0][tx]);
            unsigned int s1 = (unsigned int)__cvta_generic_to_shared(&ring[slot][1][tx]);
            unsigned int s2 = (unsigned int)__cvta_generic_to_shared(&ring[slot][2][tx]);
            cp_async8(s0, oxp + tn * (HWSZ / 2));
            cp_async8(s1, oyp + tn * (HWSZ / 2));
            cp_async8(s2, mkp + tn * (HWSZ / 2));
        }
        cp_commit();

        // ix = clamp(offy + w + fx - 1.5, -0.5, W-0.5)  (exact reduction of reference)
        float uA = o_y.x + (float)(w + fx) - 1.0f;
        float uB = o_y.y + (float)(w + 1 + fx) - 1.0f;
        float vA = o_x.x + (float)(h + fy) - 1.0f;
        float vB = o_x.y + (float)(h + fy) - 1.0f;

        float ixA = fminf(fmaxf(uA - 0.5f, -0.5f), (float)WW - 0.5f);
        float ixB = fminf(fmaxf(uB - 0.5f, -0.5f), (float)WW - 0.5f);
        float iyA = fminf(fmaxf(vA - 0.5f, -0.5f), (float)HH - 0.5f);
        float iyB = fminf(fmaxf(vB - 0.5f, -0.5f), (float)HH - 0.5f);

        float fxA = floorf(ixA), fxB = floorf(ixB);
        float fyA = floorf(iyA), fyB = floorf(iyB);
        float wx1A = ixA - fxA, wx1B = ixB - fxB;
        float wy1A = iyA - fyA, wy1B = iyB - fyB;

        int x0A = (int)fxA, x0B = (int)fxB;
        int y0A = (int)fyA, y0B = (int)fyB;
        int x0iA = max(x0A, 0);
        int x1iA = min(x0A + 1, WW - 1);
        int y0iA = max(y0A, 0);
        int y1iA = min(y0A + 1, HH - 1);
        int x0iB = max(x0B, 0);
        int x1iB = min(x0B + 1, WW - 1);
        int y0iB = max(y0B, 0);
        int y1iB = min(y0B + 1, HH - 1);

        int r0A = y0iA * WW, r1A = y1iA * WW;
        int r0B = y0iB * WW, r1B = y1iB * WW;

        // Issue all 8 gathers up front for MLP
        uint2 q00A = __ldg(gp + r0A + x0iA);
        uint2 q01A = __ldg(gp + r0A + x1iA);
        uint2 q10A = __ldg(gp + r1A + x0iA);
        uint2 q11A = __ldg(gp + r1A + x1iA);
        uint2 q00B = __ldg(gp + r0B + x0iB);
        uint2 q01B = __ldg(gp + r0B + x1iB);
        uint2 q10B = __ldg(gp + r1B + x0iB);
        uint2 q11B = __ldg(gp + r1B + x1iB);

        float coefA = vv[fy].x * hhv[fx].x * m.x;
        float coefB = vv[fy].y * hhv[fx].y * m.y;

        float w00A = coefA * (1.0f - wy1A) * (1.0f - wx1A);
        float w01A = coefA * (1.0f - wy1A) * wx1A;
        float w10A = coefA * wy1A * (1.0f - wx1A);
        float w11A = coefA * wy1A * wx1A;
        float w00B = coefB * (1.0f - wy1B) * (1.0f - wx1B);
        float w01B = coefB * (1.0f - wy1B) * wx1B;
        float w10B = coefB * wy1B * (1.0f - wx1B);
        float w11B = coefB * wy1B * wx1B;

        // Pixel A
        {
            float2 f01 = __half22float2(*reinterpret_cast<__half2*>(&q00A.x));
            float  f2  = __low2float(*reinterpret_cast<__half2*>(&q00A.y));
            a0A = fmaf(w00A, f01.x, a0A); a1A = fmaf(w00A, f01.y, a1A); a2A = fmaf(w00A, f2, a2A);
        }
        {
            float2 f01 = __half22float2(*reinterpret_cast<__half2*>(&q01A.x));
            float  f2  = __low2float(*reinterpret_cast<__half2*>(&q01A.y));
            a0A = fmaf(w01A, f01.x, a0A); a1A = fmaf(w01A, f01.y, a1A); a2A = fmaf(w01A, f2, a2A);
        }
        {
            float2 f01 = __half22float2(*reinterpret_cast<__half2*>(&q10A.x));
            float  f2  = __low2float(*reinterpret_cast<__half2*>(&q10A.y));
            a0A = fmaf(w10A, f01.x, a0A); a1A = fmaf(w10A, f01.y, a1A); a2A = fmaf(w10A, f2, a2A);
        }
        {
            float2 f01 = __half22float2(*reinterpret_cast<__half2*>(&q11A.x));
            float  f2  = __low2float(*reinterpret_cast<__half2*>(&q11A.y));
            a0A = fmaf(w11A, f01.x, a0A); a1A = fmaf(w11A, f01.y, a1A); a2A = fmaf(w11A, f2, a2A);
        }
        // Pixel B
        {
            float2 f01 = __half22float2(*reinterpret_cast<__half2*>(&q00B.x));
            float  f2  = __low2float(*reinterpret_cast<__half2*>(&q00B.y));
            a0B = fmaf(w00B, f01.x, a0B); a1B = fmaf(w00B, f01.y, a1B); a2B = fmaf(w00B, f2, a2B);
        }
        {
            float2 f01 = __half22float2(*reinterpret_cast<__half2*>(&q01B.x));
            float  f2  = __low2float(*reinterpret_cast<__half2*>(&q01B.y));
            a0B = fmaf(w01B, f01.x, a0B); a1B = fmaf(w01B, f01.y, a1B); a2B = fmaf(w01B, f2, a2B);
        }
        {
            float2 f01 = __half22float2(*reinterpret_cast<__half2*>(&q10B.x));
            float  f2  = __low2float(*reinterpret_cast<__half2*>(&q10B.y));
            a0B = fmaf(w10B, f01.x, a0B); a1B = fmaf(w10B, f01.y, a1B); a2B = fmaf(w10B, f2, a2B);
        }
        {
            float2 f01 = __half22float2(*reinterpret_cast<__half2*>(&q11B.x));
            float  f2  = __low2float(*reinterpret_cast<__half2*>(&q11B.y));
            a0B = fmaf(w11B, f01.x, a0B); a1B = fmaf(w11B, f01.y, a1B); a2B = fmaf(w11B, f2, a2B);
        }
    }

    float* ob = out + b * (CC * HWSZ) + p;
    *(float2*)(ob)            = make_float2(a0A, a0B);
    *(float2*)(ob + HWSZ)     = make_float2(a1A, a1B);
    *(float2*)(ob + 2 * HWSZ) = make_float2(a2A, a2B);
}

extern "C" void kernel_launch(void* const* d_in, const int* in_sizes, int n_in,
                              void* d_out, int out_size) {
    const float* inp   = (const float*)d_in[0];
    const float* vert  = (const float*)d_in[1];
    const float* horiz = (const float*)d_in[2];
    const float* offx  = (const float*)d_in[3];
    const float* offy  = (const float*)d_in[4];
    const float* mask  = (const float*)d_in[5];
    float* out = (float*)d_out;

    pack_kernel<<<BB * HWSZ / 4 / 256, 256>>>(inp);                                     // 512 blocks
    dsepconv_kernel<<<BB * HWSZ / 2 / 256, 256>>>(vert, horiz, offx, offy, mask, out);  // 1024 blocks
}

// round 16
// speedup vs baseline: 1.1599x; 1.1087x over previous
#include <cuda_runtime.h>
#include <cuda_fp16.h>
#include <cstdint>

// Problem constants (fixed shapes from setup_inputs)
#define BB 2
#define CC 3
#define HH 512
#define WW 512
#define FF 5
#define TT 25
#define HWSZ (HH * WW)

// Channel-interleaved fp16 copy of the input: [B, H, W, 4 halves] (4th unused).
__device__ uint2 g_packed[BB * HWSZ];

// Pack 4 pixels per thread: 3x float4 loads, 2x uint4 stores.
__global__ __launch_bounds__(256) void pack_kernel(const float* __restrict__ inp) {
    int tid = blockIdx.x * blockDim.x + threadIdx.x;   // B*H*W/4 threads
    int b = tid >> 16;
    int q = tid & (HWSZ / 4 - 1);
    int p = q * 4;
    const float* __restrict__ inb = inp + b * (CC * HWSZ) + p;
    float4 c0 = __ldg((const float4*)(inb));
    float4 c1 = __ldg((const float4*)(inb + HWSZ));
    float4 c2 = __ldg((const float4*)(inb + 2 * HWSZ));

    __half2 a01 = __floats2half2_rn(c0.x, c1.x);
    __half2 a2z = __floats2half2_rn(c2.x, 0.0f);
    __half2 b01 = __floats2half2_rn(c0.y, c1.y);
    __half2 b2z = __floats2half2_rn(c2.y, 0.0f);
    __half2 d01 = __floats2half2_rn(c0.z, c1.z);
    __half2 d2z = __floats2half2_rn(c2.z, 0.0f);
    __half2 e01 = __floats2half2_rn(c0.w, c1.w);
    __half2 e2z = __floats2half2_rn(c2.w, 0.0f);

    uint4 lo, hi;
    lo.x = *(unsigned int*)&a01; lo.y = *(unsigned int*)&a2z;
    lo.z = *(unsigned int*)&b01; lo.w = *(unsigned int*)&b2z;
    hi.x = *(unsigned int*)&d01; hi.y = *(unsigned int*)&d2z;
    hi.z = *(unsigned int*)&e01; hi.w = *(unsigned int*)&e2z;

    uint4* dst = (uint4*)(g_packed + b * HWSZ + p);
    dst[0] = lo;
    dst[1] = hi;
}

// Main kernel: R9 structure (2 horizontally-adjacent pixels per thread,
// 8 gathers batched per tap) with the streaming offx/offy/mask loads batched
// 5 taps (one fy-row) at a time: 15 independent float2 DRAM loads issued
// back-to-back -> one exposed DRAM latency per 5 taps instead of per ~2.
__global__ __launch_bounds__(256) void dsepconv_kernel(
    const float* __restrict__ vert,    // [B,F,H,W]
    const float* __restrict__ horiz,   // [B,F,H,W]
    const float* __restrict__ offx,    // [B,T,H,W]  (used for y coordinate)
    const float* __restrict__ offy,    // [B,T,H,W]  (used for x coordinate)
    const float* __restrict__ mask,    // [B,T,H,W]
    float* __restrict__ out)           // [B,C,H,W]
{
    int tid = blockIdx.x * blockDim.x + threadIdx.x;   // B*H*W/2 threads
    int b = tid >> 17;                                  // HWSZ/2 = 2^17
    int pp = tid & (HWSZ / 2 - 1);
    int p = pp * 2;                                     // even pixel index
    int h = p >> 9;
    int w = p & (WW - 1);

    const uint2* __restrict__ gp = g_packed + b * HWSZ;

    const float2* __restrict__ oxp = (const float2*)(offx + b * (TT * HWSZ) + p);
    const float2* __restrict__ oyp = (const float2*)(offy + b * (TT * HWSZ) + p);
    const float2* __restrict__ mkp = (const float2*)(mask + b * (TT * HWSZ) + p);

    // Preload separable filter values for both pixels
    float2 vv[FF], hhv[FF];
#pragma unroll
    for (int f = 0; f < FF; f++) {
        vv[f]  = __ldg((const float2*)(vert  + (b * FF + f) * HWSZ + p));
        hhv[f] = __ldg((const float2*)(horiz + (b * FF + f) * HWSZ + p));
    }

    float a0A = 0.f, a1A = 0.f, a2A = 0.f;   // pixel A accumulators
    float a0B = 0.f, a1B = 0.f, a2B = 0.f;   // pixel B accumulators

#pragma unroll
    for (int fy = 0; fy < FF; fy++) {
        // ---- Batch all streaming loads for this fy-row (15 independent
        //      DRAM loads in flight at once) ----
        float2 ox[FF], oy[FF], mk[FF];
#pragma unroll
        for (int fx = 0; fx < FF; fx++) {
            const int t = fy * FF + fx;
            ox[fx] = __ldg(oxp + t * (HWSZ / 2));   // -> y coordinate (faithful swap)
            oy[fx] = __ldg(oyp + t * (HWSZ / 2));   // -> x coordinate
            mk[fx] = __ldg(mkp + t * (HWSZ / 2));
        }

#pragma unroll
        for (int fx = 0; fx < FF; fx++) {
            float2 o_x = ox[fx];
            float2 o_y = oy[fx];
            float2 m   = mk[fx];

            // ix = clamp(offy + w + fx - 1.5, -0.5, W-0.5)  (exact reduction of reference)
            float uA = o_y.x + (float)(w + fx) - 1.0f;
            float uB = o_y.y + (float)(w + 1 + fx) - 1.0f;
            float vA = o_x.x + (float)(h + fy) - 1.0f;
            float vB = o_x.y + (float)(h + fy) - 1.0f;

            float ixA = fminf(fmaxf(uA - 0.5f, -0.5f), (float)WW - 0.5f);
            float ixB = fminf(fmaxf(uB - 0.5f, -0.5f), (float)WW - 0.5f);
            float iyA = fminf(fmaxf(vA - 0.5f, -0.5f), (float)HH - 0.5f);
            float iyB = fminf(fmaxf(vB - 0.5f, -0.5f), (float)HH - 0.5f);

            float fxA = floorf(ixA), fxB = floorf(ixB);
            float fyA = floorf(iyA), fyB = floorf(iyB);
            float wx1A = ixA - fxA, wx1B = ixB - fxB;
            float wy1A = iyA - fyA, wy1B = iyB - fyB;

            int x0A = (int)fxA, x0B = (int)fxB;
            int y0A = (int)fyA, y0B = (int)fyB;
            int x0iA = max(x0A, 0);
            int x1iA = min(x0A + 1, WW - 1);
            int y0iA = max(y0A, 0);
            int y1iA = min(y0A + 1, HH - 1);
            int x0iB = max(x0B, 0);
            int x1iB = min(x0B + 1, WW - 1);
            int y0iB = max(y0B, 0);
            int y1iB = min(y0B + 1, HH - 1);

            int r0A = y0iA * WW, r1A = y1iA * WW;
            int r0B = y0iB * WW, r1B = y1iB * WW;

            // Issue all 8 gathers up front for MLP
            uint2 q00A = __ldg(gp + r0A + x0iA);
            uint2 q01A = __ldg(gp + r0A + x1iA);
            uint2 q10A = __ldg(gp + r1A + x0iA);
            uint2 q11A = __ldg(gp + r1A + x1iA);
            uint2 q00B = __ldg(gp + r0B + x0iB);
            uint2 q01B = __ldg(gp + r0B + x1iB);
            uint2 q10B = __ldg(gp + r1B + x0iB);
            uint2 q11B = __ldg(gp + r1B + x1iB);

            float coefA = vv[fy].x * hhv[fx].x * m.x;
            float coefB = vv[fy].y * hhv[fx].y * m.y;

            float w00A = coefA * (1.0f - wy1A) * (1.0f - wx1A);
            float w01A = coefA * (1.0f - wy1A) * wx1A;
            float w10A = coefA * wy1A * (1.0f - wx1A);
            float w11A = coefA * wy1A * wx1A;
            float w00B = coefB * (1.0f - wy1B) * (1.0f - wx1B);
            float w01B = coefB * (1.0f - wy1B) * wx1B;
            float w10B = coefB * wy1B * (1.0f - wx1B);
            float w11B = coefB * wy1B * wx1B;

            // Pixel A
            {
                float2 f01 = __half22float2(*reinterpret_cast<__half2*>(&q00A.x));
                float  f2  = __low2float(*reinterpret_cast<__half2*>(&q00A.y));
                a0A = fmaf(w00A, f01.x, a0A); a1A = fmaf(w00A, f01.y, a1A); a2A = fmaf(w00A, f2, a2A);
            }
            {
                float2 f01 = __half22float2(*reinterpret_cast<__half2*>(&q01A.x));
                float  f2  = __low2float(*reinterpret_cast<__half2*>(&q01A.y));
                a0A = fmaf(w01A, f01.x, a0A); a1A = fmaf(w01A, f01.y, a1A); a2A = fmaf(w01A, f2, a2A);
            }
            {
                float2 f01 = __half22float2(*reinterpret_cast<__half2*>(&q10A.x));
                float  f2  = __low2float(*reinterpret_cast<__half2*>(&q10A.y));
                a0A = fmaf(w10A, f01.x, a0A); a1A = fmaf(w10A, f01.y, a1A); a2A = fmaf(w10A, f2, a2A);
            }
            {
                float2 f01 = __half22float2(*reinterpret_cast<__half2*>(&q11A.x));
                float  f2  = __low2float(*reinterpret_cast<__half2*>(&q11A.y));
                a0A = fmaf(w11A, f01.x, a0A); a1A = fmaf(w11A, f01.y, a1A); a2A = fmaf(w11A, f2, a2A);
            }
            // Pixel B
            {
                float2 f01 = __half22float2(*reinterpret_cast<__half2*>(&q00B.x));
                float  f2  = __low2float(*reinterpret_cast<__half2*>(&q00B.y));
                a0B = fmaf(w00B, f01.x, a0B); a1B = fmaf(w00B, f01.y, a1B); a2B = fmaf(w00B, f2, a2B);
            }
            {
                float2 f01 = __half22float2(*reinterpret_cast<__half2*>(&q01B.x));
                float  f2  = __low2float(*reinterpret_cast<__half2*>(&q01B.y));
                a0B = fmaf(w01B, f01.x, a0B); a1B = fmaf(w01B, f01.y, a1B); a2B = fmaf(w01B, f2, a2B);
            }
            {
                float2 f01 = __half22float2(*reinterpret_cast<__half2*>(&q10B.x));
                float  f2  = __low2float(*reinterpret_cast<__half2*>(&q10B.y));
                a0B = fmaf(w10B, f01.x, a0B); a1B = fmaf(w10B, f01.y, a1B); a2B = fmaf(w10B, f2, a2B);
            }
            {
                float2 f01 = __half22float2(*reinterpret_cast<__half2*>(&q11B.x));
                float  f2  = __low2float(*reinterpret_cast<__half2*>(&q11B.y));
                a0B = fmaf(w11B, f01.x, a0B); a1B = fmaf(w11B, f01.y, a1B); a2B = fmaf(w11B, f2, a2B);
            }
        }
    }

    float* ob = out + b * (CC * HWSZ) + p;
    *(float2*)(ob)            = make_float2(a0A, a0B);
    *(float2*)(ob + HWSZ)     = make_float2(a1A, a1B);
    *(float2*)(ob + 2 * HWSZ) = make_float2(a2A, a2B);
}

extern "C" void kernel_launch(void* const* d_in, const int* in_sizes, int n_in,
                              void* d_out, int out_size) {
    const float* inp   = (const float*)d_in[0];
    const float* vert  = (const float*)d_in[1];
    const float* horiz = (const float*)d_in[2];
    const float* offx  = (const float*)d_in[3];
    const float* offy  = (const float*)d_in[4];
    const float* mask  = (const float*)d_in[5];
    float* out = (float*)d_out;

    pack_kernel<<<BB * HWSZ / 4 / 256, 256>>>(inp);                                     // 512 blocks
    dsepconv_kernel<<<BB * HWSZ / 2 / 256, 256>>>(vert, horiz, offx, offy, mask, out);  // 1024 blocks
}